// round 1
// baseline (speedup 1.0000x reference)
#include <cuda_runtime.h>
#include <cuda_bf16.h>
#include <math.h>

// Problem constants
#define NN 262144          // nodes
#define EE 524288          // edges
#define GG 8192            // graphs
#define DD 300
#define DD2 600
#define LL 5
#define HGC 2348           // D + 2048
#define H1 1200            // 4*D
#define NT 128             // num_task

// ---------------- scratch (device globals; no allocations) ----------------
__device__ float g_h  [(size_t)NN * DD];
__device__ float g_hl [(size_t)NN * DD];
__device__ float g_acc[(size_t)NN * DD];
__device__ float g_y1 [(size_t)NN * DD2];
__device__ float g_y2 [(size_t)NN * DD];
__device__ float g_vn [(size_t)GG * DD];
__device__ float g_vt [(size_t)GG * DD];
__device__ float g_u1 [(size_t)GG * DD2];
__device__ float g_u2 [(size_t)GG * DD];
__device__ float g_hg [(size_t)GG * HGC];
__device__ float g_t1 [(size_t)GG * H1];
__device__ float g_stats[2 * DD2];   // [0:C) sum, [C:2C) sumsq
__device__ float g_scale[DD2];
__device__ float g_shift[DD2];

// ---------------- small utility kernels ----------------
__global__ void k_zero(float* p, size_t n) {
    size_t i = (size_t)blockIdx.x * blockDim.x + threadIdx.x;
    if (i < n) p[i] = 0.f;
}

__global__ void k_embed(const int* __restrict__ x_atom,
                        const float* __restrict__ atom_emb,
                        float* __restrict__ h) {
    size_t idx = (size_t)blockIdx.x * blockDim.x + threadIdx.x;
    if (idx >= (size_t)NN * DD) return;
    int i = (int)(idx / DD);
    int c = (int)(idx - (size_t)i * DD);
    h[idx] = atom_emb[(size_t)x_atom[i] * DD + c];
}

// hl = h + vn[batch]; acc = (1+eps_l)*hl; optionally vt[batch] += hl
__global__ void k_hl_acc(const float* __restrict__ h,
                         const float* __restrict__ vn,
                         const int* __restrict__ batch,
                         const float* __restrict__ eps, int l,
                         float* __restrict__ hl,
                         float* __restrict__ acc,
                         float* __restrict__ vt, int doVt) {
    size_t idx = (size_t)blockIdx.x * blockDim.x + threadIdx.x;
    if (idx >= (size_t)NN * DD) return;
    int i = (int)(idx / DD);
    int c = (int)(idx - (size_t)i * DD);
    int b = batch[i];
    float v = h[idx] + vn[(size_t)b * DD + c];
    hl[idx] = v;
    acc[idx] = (1.f + eps[l]) * v;
    if (doVt) atomicAdd(&vt[(size_t)b * DD + c], v);
}

// one block per edge: acc[dst] += relu(hl[src] + edge_emb[attr])
__global__ void k_edge_scatter(const float* __restrict__ hl,
                               const float* __restrict__ eemb,   // [5, D] for this layer
                               const int* __restrict__ src,
                               const int* __restrict__ dst,
                               const int* __restrict__ eattr,
                               float* __restrict__ acc) {
    int e = blockIdx.x;
    int s = src[e], d = dst[e], a = eattr[e];
    const float* hs = hl + (size_t)s * DD;
    const float* em = eemb + (size_t)a * DD;
    float* out = acc + (size_t)d * DD;
    for (int c = threadIdx.x; c < DD; c += blockDim.x) {
        float m = hs[c] + em[c];
        if (m > 0.f) atomicAdd(&out[c], m);
    }
}

// column sums / sumsq : thread t -> column t%C, 128 row-strides
__global__ void k_bnstats(const float* __restrict__ X, int M, int C,
                          float* __restrict__ stats) {
    int t = blockIdx.x * blockDim.x + threadIdx.x;
    int total = C * 128;
    if (t >= total) return;
    int c = t % C;
    int r0 = t / C;
    float s = 0.f, s2 = 0.f;
    for (int r = r0; r < M; r += 128) {
        float v = X[(size_t)r * C + c];
        s += v; s2 += v * v;
    }
    atomicAdd(&stats[c], s);
    atomicAdd(&stats[C + c], s2);
}

__global__ void k_bnfinal(const float* __restrict__ stats,
                          const float* __restrict__ gamma,
                          const float* __restrict__ beta,
                          int M, int C,
                          float* __restrict__ scale, float* __restrict__ shift) {
    int c = blockIdx.x * blockDim.x + threadIdx.x;
    if (c >= C) return;
    float inv = 1.f / (float)M;
    float mean = stats[c] * inv;
    float var  = stats[C + c] * inv - mean * mean;
    float s = gamma[c] * rsqrtf(var + 1e-5f);
    scale[c] = s;
    shift[c] = beta[c] - mean * s;
}

__global__ void k_bnapply(const float* __restrict__ X, float* __restrict__ Y,
                          size_t total, int C,
                          const float* __restrict__ scale,
                          const float* __restrict__ shift, int relu) {
    size_t idx = (size_t)blockIdx.x * blockDim.x + threadIdx.x;
    if (idx >= total) return;
    int c = (int)(idx % C);
    float v = X[idx] * scale[c] + shift[c];
    if (relu) v = fmaxf(v, 0.f);
    Y[idx] = v;
}

__global__ void k_hg_init(const float* __restrict__ fp, float* __restrict__ hg) {
    size_t idx = (size_t)blockIdx.x * blockDim.x + threadIdx.x;
    if (idx >= (size_t)GG * HGC) return;
    int g = (int)(idx / HGC);
    int c = (int)(idx - (size_t)g * HGC);
    hg[idx] = (c < DD) ? 0.f : fp[(size_t)g * 2048 + (c - DD)];
}

__global__ void k_pool(const float* __restrict__ h, const int* __restrict__ batch,
                       float* __restrict__ hg) {
    size_t idx = (size_t)blockIdx.x * blockDim.x + threadIdx.x;
    if (idx >= (size_t)NN * DD) return;
    int i = (int)(idx / DD);
    int c = (int)(idx - (size_t)i * DD);
    atomicAdd(&hg[(size_t)batch[i] * HGC + c], h[idx]);
}

// ---------------- SGEMM 128x128x16, 8x8 per thread ----------------
#define BM 128
#define BN 128
#define BK 16
#define TM 8
#define TN 8

__device__ __forceinline__ float gelu_tanh(float x) {
    const float k0 = 0.7978845608028654f;   // sqrt(2/pi)
    const float k1 = 0.044715f;
    float x3 = x * x * x;
    return 0.5f * x * (1.f + tanhf(k0 * (x + k1 * x3)));
}

// act: 0=none, 1=relu, 2=gelu(tanh). M must be a multiple of BM.
__global__ __launch_bounds__(256)
void k_sgemm(int M, int N, int K,
             const float* __restrict__ A, const float* __restrict__ B,
             const float* __restrict__ bias, float* __restrict__ C, int act) {
    __shared__ float As[BK][BM + 1];
    __shared__ float Bs[BK][BN];
    int tid = threadIdx.x;
    int tx = tid % (BN / TN);   // 0..15
    int ty = tid / (BN / TN);   // 0..15
    int rowBase = blockIdx.y * BM;
    int colBase = blockIdx.x * BN;

    float acc[TM][TN];
    #pragma unroll
    for (int i = 0; i < TM; i++)
        #pragma unroll
        for (int j = 0; j < TN; j++) acc[i][j] = 0.f;

    for (int k0 = 0; k0 < K; k0 += BK) {
        #pragma unroll
        for (int i = 0; i < (BM * BK) / 256; i++) {
            int idx = tid + i * 256;
            int r = idx / BK, c = idx % BK;
            float v = 0.f;
            if (k0 + c < K) v = A[(size_t)(rowBase + r) * K + (k0 + c)];
            As[c][r] = v;
        }
        #pragma unroll
        for (int i = 0; i < (BK * BN) / 256; i++) {
            int idx = tid + i * 256;
            int r = idx / BN, c = idx % BN;
            float v = 0.f;
            if ((k0 + r) < K && (colBase + c) < N) v = B[(size_t)(k0 + r) * N + (colBase + c)];
            Bs[r][c] = v;
        }
        __syncthreads();
        #pragma unroll
        for (int kk = 0; kk < BK; kk++) {
            float ra[TM], rb[TN];
            #pragma unroll
            for (int i = 0; i < TM; i++) ra[i] = As[kk][ty * TM + i];
            #pragma unroll
            for (int j = 0; j < TN; j++) rb[j] = Bs[kk][tx * TN + j];
            #pragma unroll
            for (int i = 0; i < TM; i++)
                #pragma unroll
                for (int j = 0; j < TN; j++)
                    acc[i][j] = fmaf(ra[i], rb[j], acc[i][j]);
        }
        __syncthreads();
    }

    #pragma unroll
    for (int i = 0; i < TM; i++) {
        int row = rowBase + ty * TM + i;
        #pragma unroll
        for (int j = 0; j < TN; j++) {
            int col = colBase + tx * TN + j;
            if (col < N) {
                float v = acc[i][j] + bias[col];
                if (act == 1) v = fmaxf(v, 0.f);
                else if (act == 2) v = gelu_tanh(v);
                C[(size_t)row * N + col] = v;
            }
        }
    }
}

// ---------------- host orchestration ----------------
static inline int cdiv(long long a, long long b) { return (int)((a + b - 1) / b); }

extern "C" void kernel_launch(void* const* d_in, const int* in_sizes, int n_in,
                              void* d_out, int out_size) {
    const int*   x_atom  = (const int*)  d_in[0];
    const int*   src     = (const int*)  d_in[1];
    const int*   dst     = (const int*)  d_in[2];
    const int*   eattr   = (const int*)  d_in[3];
    const int*   batch   = (const int*)  d_in[4];
    const float* fp      = (const float*)d_in[5];
    const float* atom_emb= (const float*)d_in[6];
    const float* edge_emb= (const float*)d_in[7];
    const float* eps     = (const float*)d_in[8];
    const float* W1  = (const float*)d_in[9];
    const float* b1  = (const float*)d_in[10];
    const float* g1  = (const float*)d_in[11];
    const float* be1 = (const float*)d_in[12];
    const float* W2  = (const float*)d_in[13];
    const float* b2  = (const float*)d_in[14];
    const float* bng = (const float*)d_in[15];
    const float* bnb = (const float*)d_in[16];
    const float* vW1 = (const float*)d_in[17];
    const float* vb1 = (const float*)d_in[18];
    const float* vg1 = (const float*)d_in[19];
    const float* vbe1= (const float*)d_in[20];
    const float* vW2 = (const float*)d_in[21];
    const float* vb2 = (const float*)d_in[22];
    const float* vg2 = (const float*)d_in[23];
    const float* vbe2= (const float*)d_in[24];
    const float* pW1 = (const float*)d_in[25];
    const float* pb1 = (const float*)d_in[26];
    const float* pW2 = (const float*)d_in[27];
    const float* pb2 = (const float*)d_in[28];
    float* out = (float*)d_out;

    float *p_h, *p_hl, *p_acc, *p_y1, *p_y2, *p_vn, *p_vt, *p_u1, *p_u2,
          *p_hg, *p_t1, *p_stats, *p_scale, *p_shift;
    cudaGetSymbolAddress((void**)&p_h,    g_h);
    cudaGetSymbolAddress((void**)&p_hl,   g_hl);
    cudaGetSymbolAddress((void**)&p_acc,  g_acc);
    cudaGetSymbolAddress((void**)&p_y1,   g_y1);
    cudaGetSymbolAddress((void**)&p_y2,   g_y2);
    cudaGetSymbolAddress((void**)&p_vn,   g_vn);
    cudaGetSymbolAddress((void**)&p_vt,   g_vt);
    cudaGetSymbolAddress((void**)&p_u1,   g_u1);
    cudaGetSymbolAddress((void**)&p_u2,   g_u2);
    cudaGetSymbolAddress((void**)&p_hg,   g_hg);
    cudaGetSymbolAddress((void**)&p_t1,   g_t1);
    cudaGetSymbolAddress((void**)&p_stats,g_stats);
    cudaGetSymbolAddress((void**)&p_scale,g_scale);
    cudaGetSymbolAddress((void**)&p_shift,g_shift);

    const size_t ND  = (size_t)NN * DD;
    const size_t GD  = (size_t)GG * DD;

    // vn = 0 ; h = atom_emb[x_atom]
    k_zero<<<cdiv(GD, 256), 256>>>(p_vn, GD);
    k_embed<<<cdiv(ND, 256), 256>>>(x_atom, atom_emb, p_h);

    for (int l = 0; l < LL; l++) {
        int doVt = (l < LL - 1);
        if (doVt)
            cudaMemcpyAsync(p_vt, p_vn, GD * sizeof(float), cudaMemcpyDeviceToDevice);

        k_hl_acc<<<cdiv(ND, 256), 256>>>(p_h, p_vn, batch, eps, l,
                                         p_hl, p_acc, p_vt, doVt);

        k_edge_scatter<<<EE, 128>>>(p_hl, edge_emb + (size_t)l * 5 * DD,
                                    src, dst, eattr, p_acc);

        // GEMM1: [NN,300] @ [300,600]
        {
            dim3 grid(cdiv(DD2, BN), NN / BM);
            k_sgemm<<<grid, 256>>>(NN, DD2, DD, p_acc,
                                   W1 + (size_t)l * DD * DD2, b1 + (size_t)l * DD2,
                                   p_y1, 0);
        }
        k_zero<<<cdiv(2 * DD2, 256), 256>>>(p_stats, 2 * DD2);
        k_bnstats<<<cdiv((long long)DD2 * 128, 256), 256>>>(p_y1, NN, DD2, p_stats);
        k_bnfinal<<<cdiv(DD2, 256), 256>>>(p_stats, g1 + (size_t)l * DD2,
                                           be1 + (size_t)l * DD2, NN, DD2,
                                           p_scale, p_shift);
        k_bnapply<<<cdiv((size_t)NN * DD2, 256), 256>>>(p_y1, p_y1,
                                                        (size_t)NN * DD2, DD2,
                                                        p_scale, p_shift, 1);

        // GEMM2: [NN,600] @ [600,300]
        {
            dim3 grid(cdiv(DD, BN), NN / BM);
            k_sgemm<<<grid, 256>>>(NN, DD, DD2, p_y1,
                                   W2 + (size_t)l * DD2 * DD, b2 + (size_t)l * DD,
                                   p_y2, 0);
        }
        k_zero<<<cdiv(2 * DD, 256), 256>>>(p_stats, 2 * DD);
        k_bnstats<<<cdiv((long long)DD * 128, 256), 256>>>(p_y2, NN, DD, p_stats);
        k_bnfinal<<<cdiv(DD, 256), 256>>>(p_stats, bng + (size_t)l * DD,
                                          bnb + (size_t)l * DD, NN, DD,
                                          p_scale, p_shift);
        k_bnapply<<<cdiv(ND, 256), 256>>>(p_y2, p_h, ND, DD,
                                          p_scale, p_shift, doVt ? 1 : 0);

        // virtual node update
        if (doVt) {
            dim3 grid1(cdiv(DD2, BN), GG / BM);
            k_sgemm<<<grid1, 256>>>(GG, DD2, DD, p_vt,
                                    vW1 + (size_t)l * DD * DD2, vb1 + (size_t)l * DD2,
                                    p_u1, 0);
            k_zero<<<cdiv(2 * DD2, 256), 256>>>(p_stats, 2 * DD2);
            k_bnstats<<<cdiv((long long)DD2 * 128, 256), 256>>>(p_u1, GG, DD2, p_stats);
            k_bnfinal<<<cdiv(DD2, 256), 256>>>(p_stats, vg1 + (size_t)l * DD2,
                                               vbe1 + (size_t)l * DD2, GG, DD2,
                                               p_scale, p_shift);
            k_bnapply<<<cdiv((size_t)GG * DD2, 256), 256>>>(p_u1, p_u1,
                                                            (size_t)GG * DD2, DD2,
                                                            p_scale, p_shift, 1);

            dim3 grid2(cdiv(DD, BN), GG / BM);
            k_sgemm<<<grid2, 256>>>(GG, DD, DD2, p_u1,
                                    vW2 + (size_t)l * DD2 * DD, vb2 + (size_t)l * DD,
                                    p_u2, 0);
            k_zero<<<cdiv(2 * DD, 256), 256>>>(p_stats, 2 * DD);
            k_bnstats<<<cdiv((long long)DD * 128, 256), 256>>>(p_u2, GG, DD, p_stats);
            k_bnfinal<<<cdiv(DD, 256), 256>>>(p_stats, vg2 + (size_t)l * DD,
                                              vbe2 + (size_t)l * DD, GG, DD,
                                              p_scale, p_shift);
            k_bnapply<<<cdiv(GD, 256), 256>>>(p_u2, p_vn, GD, DD,
                                              p_scale, p_shift, 1);
        }
    }

    // head: pool + concat fp, MLP
    k_hg_init<<<cdiv((size_t)GG * HGC, 256), 256>>>(fp, p_hg);
    k_pool<<<cdiv(ND, 256), 256>>>(p_h, batch, p_hg);

    {
        dim3 grid(cdiv(H1, BN), GG / BM);
        k_sgemm<<<grid, 256>>>(GG, H1, HGC, p_hg, pW1, pb1, p_t1, 2 /*gelu*/);
    }
    {
        dim3 grid(cdiv(NT, BN), GG / BM);
        k_sgemm<<<grid, 256>>>(GG, NT, H1, p_t1, pW2, pb2, out, 0);
    }
}

// round 4
// speedup vs baseline: 3.2708x; 3.2708x over previous
#include <cuda_runtime.h>
#include <cuda_bf16.h>
#include <cstdint>
#include <math.h>

// Problem constants
#define NN 262144
#define EE 524288
#define GG 8192
#define DD 300
#define DD2 600
#define LL 5
#define HGC 2348
#define H1 1200
#define NT 128

// ---------------- scratch (device globals) ----------------
__device__ float g_h  [(size_t)NN * DD];
__device__ float g_hl [(size_t)NN * DD];
__device__ float g_acc[(size_t)NN * DD];
__device__ float g_y1 [(size_t)NN * DD2];
__device__ float g_y2 [(size_t)NN * DD];
__device__ float g_vn [(size_t)GG * DD];
__device__ float g_vt [(size_t)GG * DD];
__device__ float g_u1 [(size_t)GG * DD2];
__device__ float g_u2 [(size_t)GG * DD];
__device__ float g_hg [(size_t)GG * HGC];
__device__ float g_t1 [(size_t)GG * H1];
__device__ float g_stats[2 * DD2];
__device__ float g_scale[DD2];
__device__ float g_shift[DD2];

// ---------------- utility kernels ----------------
__global__ void k_zero(float* p, size_t n) {
    size_t i = (size_t)blockIdx.x * blockDim.x + threadIdx.x;
    if (i < n) p[i] = 0.f;
}

__global__ void k_embed(const int* __restrict__ x_atom,
                        const float* __restrict__ atom_emb,
                        float* __restrict__ h) {
    size_t idx4 = (size_t)blockIdx.x * blockDim.x + threadIdx.x;
    size_t tot4 = (size_t)NN * DD / 4;
    if (idx4 >= tot4) return;
    int i  = (int)(idx4 / (DD / 4));
    int c4 = (int)(idx4 - (size_t)i * (DD / 4));
    const float4* srcv = (const float4*)(atom_emb + (size_t)x_atom[i] * DD);
    ((float4*)h)[idx4] = srcv[c4];
}

// hl = h + vn[batch]; acc = (1+eps_l)*hl
__global__ void k_hl_acc(const float* __restrict__ h,
                         const float* __restrict__ vn,
                         const int* __restrict__ batch,
                         const float* __restrict__ eps, int l,
                         float* __restrict__ hl,
                         float* __restrict__ acc) {
    size_t idx4 = (size_t)blockIdx.x * blockDim.x + threadIdx.x;
    size_t tot4 = (size_t)NN * DD / 4;
    if (idx4 >= tot4) return;
    int i  = (int)(idx4 / (DD / 4));
    int c4 = (int)(idx4 - (size_t)i * (DD / 4));
    int b  = batch[i];
    float e = 1.f + eps[l];
    float4 hv = ((const float4*)h)[idx4];
    float4 vv = ((const float4*)(vn + (size_t)b * DD))[c4];
    float4 o, a;
    o.x = hv.x + vv.x; o.y = hv.y + vv.y; o.z = hv.z + vv.z; o.w = hv.w + vv.w;
    a.x = e * o.x; a.y = e * o.y; a.z = e * o.z; a.w = e * o.w;
    ((float4*)hl)[idx4] = o;
    ((float4*)acc)[idx4] = a;
}

// edge scatter: 4 edges / 300-thread block
__global__ void k_edge(const float* __restrict__ hl,
                       const float* __restrict__ eemb,   // [5, D]
                       const int* __restrict__ src,
                       const int* __restrict__ dst,
                       const int* __restrict__ eattr,
                       float* __restrict__ acc) {
    int sub = threadIdx.x / 75;
    int c4  = threadIdx.x % 75;
    int e = blockIdx.x * 4 + sub;
    int s = src[e], d = dst[e], a = eattr[e];
    float4 hv = *(const float4*)(hl   + (size_t)s * DD + c4 * 4);
    float4 ev = *(const float4*)(eemb + (size_t)a * DD + c4 * 4);
    float* out = acc + (size_t)d * DD + c4 * 4;
    float m;
    m = hv.x + ev.x; if (m > 0.f) atomicAdd(out + 0, m);
    m = hv.y + ev.y; if (m > 0.f) atomicAdd(out + 1, m);
    m = hv.z + ev.z; if (m > 0.f) atomicAdd(out + 2, m);
    m = hv.w + ev.w; if (m > 0.f) atomicAdd(out + 3, m);
}

__device__ __forceinline__ int lbound(const int* __restrict__ arr, int n, int val) {
    int lo = 0, hi = n;
    while (lo < hi) { int mid = (lo + hi) >> 1; if (arr[mid] < val) lo = mid + 1; else hi = mid; }
    return lo;
}

__global__ void k_vt(const float* __restrict__ hl, const int* __restrict__ batch,
                     const float* __restrict__ vn, float* __restrict__ vt) {
    int g = blockIdx.x;
    __shared__ int ss, se;
    if (threadIdx.x == 0) { ss = lbound(batch, NN, g); se = lbound(batch, NN, g + 1); }
    __syncthreads();
    int s0 = ss, s1 = se;
    for (int c = threadIdx.x; c < DD; c += blockDim.x) {
        float s = vn[(size_t)g * DD + c];
        for (int r = s0; r < s1; r++) s += hl[(size_t)r * DD + c];
        vt[(size_t)g * DD + c] = s;
    }
}

__global__ void k_pool(const float* __restrict__ h, const int* __restrict__ batch,
                       const float* __restrict__ fp, float* __restrict__ hg) {
    int g = blockIdx.x;
    __shared__ int ss, se;
    if (threadIdx.x == 0) { ss = lbound(batch, NN, g); se = lbound(batch, NN, g + 1); }
    __syncthreads();
    int s0 = ss, s1 = se;
    for (int c = threadIdx.x; c < HGC; c += blockDim.x) {
        float v;
        if (c < DD) {
            v = 0.f;
            for (int r = s0; r < s1; r++) v += h[(size_t)r * DD + c];
        } else {
            v = fp[(size_t)g * 2048 + (c - DD)];
        }
        hg[(size_t)g * HGC + c] = v;
    }
}

__global__ void k_bnfinal(const float* __restrict__ stats,
                          const float* __restrict__ gamma,
                          const float* __restrict__ beta,
                          int M, int C,
                          float* __restrict__ scale, float* __restrict__ shift) {
    int c = blockIdx.x * blockDim.x + threadIdx.x;
    if (c >= C) return;
    float inv = 1.f / (float)M;
    float mean = stats[c] * inv;
    float var  = stats[C + c] * inv - mean * mean;
    float s = gamma[c] * rsqrtf(var + 1e-5f);
    scale[c] = s;
    shift[c] = beta[c] - mean * s;
}

__global__ void k_bnapply(const float* __restrict__ X, float* __restrict__ Y,
                          size_t total4, int C4,
                          const float* __restrict__ scale,
                          const float* __restrict__ shift, int relu) {
    size_t idx4 = (size_t)blockIdx.x * blockDim.x + threadIdx.x;
    if (idx4 >= total4) return;
    int c4 = (int)(idx4 % C4) * 4;
    float4 x = ((const float4*)X)[idx4];
    float4 o;
    o.x = x.x * scale[c4 + 0] + shift[c4 + 0];
    o.y = x.y * scale[c4 + 1] + shift[c4 + 1];
    o.z = x.z * scale[c4 + 2] + shift[c4 + 2];
    o.w = x.w * scale[c4 + 3] + shift[c4 + 3];
    if (relu) {
        o.x = fmaxf(o.x, 0.f); o.y = fmaxf(o.y, 0.f);
        o.z = fmaxf(o.z, 0.f); o.w = fmaxf(o.w, 0.f);
    }
    ((float4*)Y)[idx4] = o;
}

// ---------------- bf16-split (bf16x3) tensor-core GEMM ----------------
// C[M,N] = act( A'[M,K] @ B[K,N] + bias ), A' optionally relu(A*scaleA[k]+shiftA[k])
// A*B computed as Ahi*Bhi + Ahi*Blo + Alo*Bhi, fp32 accumulate.
// Optional column sum/sumsq of pre-activation C into stats.

__device__ __forceinline__ uint32_t packbf2(float a, float b) {
    __nv_bfloat162 t = __floats2bfloat162_rn(a, b);   // a -> low half
    return *reinterpret_cast<uint32_t*>(&t);
}
__device__ __forceinline__ float bf_hi(float x) {
    return __bfloat162float(__float2bfloat16_rn(x));
}

__device__ __forceinline__ void mma_bf16(float* d, const uint32_t* a, const uint32_t* b) {
    asm volatile(
        "mma.sync.aligned.m16n8k16.row.col.f32.bf16.bf16.f32 "
        "{%0,%1,%2,%3}, {%4,%5,%6,%7}, {%8,%9}, {%0,%1,%2,%3};\n"
        : "+f"(d[0]), "+f"(d[1]), "+f"(d[2]), "+f"(d[3])
        : "r"(a[0]), "r"(a[1]), "r"(a[2]), "r"(a[3]),
          "r"(b[0]), "r"(b[1]));
}

__device__ __forceinline__ float gelu_tanh(float x) {
    const float k0 = 0.7978845608028654f;
    const float k1 = 0.044715f;
    float x3 = x * x * x;
    return 0.5f * x * (1.f + tanhf(k0 * (x + k1 * x3)));
}

#define SMP 136   // padded word stride (reads conflict-free: tg*8+gID unique mod 32)

__global__ __launch_bounds__(256, 2)
void k_mma(int M, int N, int K,
           const float* __restrict__ A, const float* __restrict__ B,
           const float* __restrict__ bias, float* __restrict__ C,
           const float* __restrict__ aScale, const float* __restrict__ aShift,
           float* stats, int act) {
    // [buf][kpair(8)][word] ; word = row (A) or col (B)
    __shared__ __align__(16) uint32_t AsH[2][8][SMP];
    __shared__ __align__(16) uint32_t AsL[2][8][SMP];
    __shared__ __align__(16) uint32_t BsH[2][8][SMP];
    __shared__ __align__(16) uint32_t BsL[2][8][SMP];

    const int tid  = threadIdx.x;
    const int lane = tid & 31;
    const int warp = tid >> 5;
    const int warpM = warp >> 2;        // 0..1
    const int warpN = warp & 3;         // 0..3
    const int gID = lane >> 2;          // 0..7
    const int tg  = lane & 3;           // 0..3
    const int rowBase = blockIdx.y * 128;
    const int colBase = blockIdx.x * 128;
    const bool aTrans = (aScale != nullptr);

    float acc[4][4][4];
    #pragma unroll
    for (int i = 0; i < 4; i++)
        #pragma unroll
        for (int j = 0; j < 4; j++)
            #pragma unroll
            for (int r = 0; r < 4; r++) acc[i][j][r] = 0.f;

    const int KT = (K + 15) / 16;

    // prefetch registers
    float4 aV[2];          // A: 2 slots (row, k-quad)
    float4 bV0, bV1;       // B: one (kpair,col4) slot -> rows 2kp, 2kp+1

    // B loader mapping: kp = tid>>5 (0..7), col4 = tid&31
    const int bKp  = tid >> 5;
    const int bC4  = tid & 31;

    auto loadTile = [&](int t) {
        int k0 = t * 16;
        #pragma unroll
        for (int i = 0; i < 2; i++) {
            int tl = tid + i * 256;
            int row = tl >> 2, c4 = tl & 3;
            int gk = k0 + c4 * 4;
            float4 v = make_float4(0.f, 0.f, 0.f, 0.f);
            if (gk < K) {
                v = *(const float4*)(A + (size_t)(rowBase + row) * K + gk);
                if (aTrans) {
                    v.x = fmaxf(v.x * __ldg(aScale + gk + 0) + __ldg(aShift + gk + 0), 0.f);
                    v.y = fmaxf(v.y * __ldg(aScale + gk + 1) + __ldg(aShift + gk + 1), 0.f);
                    v.z = fmaxf(v.z * __ldg(aScale + gk + 2) + __ldg(aShift + gk + 2), 0.f);
                    v.w = fmaxf(v.w * __ldg(aScale + gk + 3) + __ldg(aShift + gk + 3), 0.f);
                }
            }
            aV[i] = v;
        }
        int gr0 = k0 + 2 * bKp;
        int gc  = colBase + bC4 * 4;
        bV0 = make_float4(0.f, 0.f, 0.f, 0.f);
        bV1 = make_float4(0.f, 0.f, 0.f, 0.f);
        if (gc < N) {
            if (gr0     < K) bV0 = *(const float4*)(B + (size_t)gr0       * N + gc);
            if (gr0 + 1 < K) bV1 = *(const float4*)(B + (size_t)(gr0 + 1) * N + gc);
        }
    };

    auto storeTile = [&](int buf) {
        #pragma unroll
        for (int i = 0; i < 2; i++) {
            int tl = tid + i * 256;
            int row = tl >> 2, c4 = tl & 3;
            float4 v = aV[i];
            float hx = bf_hi(v.x), hy = bf_hi(v.y), hz = bf_hi(v.z), hw = bf_hi(v.w);
            AsH[buf][c4 * 2    ][row] = packbf2(hx, hy);
            AsH[buf][c4 * 2 + 1][row] = packbf2(hz, hw);
            AsL[buf][c4 * 2    ][row] = packbf2(v.x - hx, v.y - hy);
            AsL[buf][c4 * 2 + 1][row] = packbf2(v.z - hz, v.w - hw);
        }
        float h0x = bf_hi(bV0.x), h0y = bf_hi(bV0.y), h0z = bf_hi(bV0.z), h0w = bf_hi(bV0.w);
        float h1x = bf_hi(bV1.x), h1y = bf_hi(bV1.y), h1z = bf_hi(bV1.z), h1w = bf_hi(bV1.w);
        uint4 hv = make_uint4(packbf2(h0x, h1x), packbf2(h0y, h1y),
                              packbf2(h0z, h1z), packbf2(h0w, h1w));
        uint4 lv = make_uint4(packbf2(bV0.x - h0x, bV1.x - h1x),
                              packbf2(bV0.y - h0y, bV1.y - h1y),
                              packbf2(bV0.z - h0z, bV1.z - h1z),
                              packbf2(bV0.w - h0w, bV1.w - h1w));
        *(uint4*)&BsH[buf][bKp][bC4 * 4] = hv;
        *(uint4*)&BsL[buf][bKp][bC4 * 4] = lv;
    };

    loadTile(0);
    storeTile(0);
    __syncthreads();

    for (int t = 0; t < KT; t++) {
        int buf = t & 1;
        if (t + 1 < KT) loadTile(t + 1);

        uint32_t bh[4][2], bl[4][2];
        #pragma unroll
        for (int nt = 0; nt < 4; nt++) {
            int c = warpN * 32 + nt * 8 + gID;
            bh[nt][0] = BsH[buf][tg    ][c];
            bh[nt][1] = BsH[buf][tg + 4][c];
            bl[nt][0] = BsL[buf][tg    ][c];
            bl[nt][1] = BsL[buf][tg + 4][c];
        }
        #pragma unroll
        for (int mt = 0; mt < 4; mt++) {
            int r0 = warpM * 64 + mt * 16 + gID;
            uint32_t ah[4], al[4];
            ah[0] = AsH[buf][tg    ][r0];
            ah[1] = AsH[buf][tg    ][r0 + 8];
            ah[2] = AsH[buf][tg + 4][r0];
            ah[3] = AsH[buf][tg + 4][r0 + 8];
            al[0] = AsL[buf][tg    ][r0];
            al[1] = AsL[buf][tg    ][r0 + 8];
            al[2] = AsL[buf][tg + 4][r0];
            al[3] = AsL[buf][tg + 4][r0 + 8];
            #pragma unroll
            for (int nt = 0; nt < 4; nt++) {
                mma_bf16(acc[mt][nt], ah, bh[nt]);
                mma_bf16(acc[mt][nt], ah, bl[nt]);
                mma_bf16(acc[mt][nt], al, bh[nt]);
            }
        }

        if (t + 1 < KT) storeTile(buf ^ 1);
        __syncthreads();
    }

    // ---- epilogue ----
    const bool doStats = (stats != nullptr);
    float* sstat = reinterpret_cast<float*>(&AsH[0][0][0]);  // 256 floats scratch
    if (doStats) {
        if (tid < 256) sstat[tid] = 0.f;
        __syncthreads();
    }

    #pragma unroll
    for (int nt = 0; nt < 4; nt++) {
        #pragma unroll
        for (int p = 0; p < 2; p++) {
            int lc = warpN * 32 + nt * 8 + 2 * tg + p;
            int col = colBase + lc;
            bool cv = col < N;
            float bs = cv ? __ldg(bias + col) : 0.f;
            float s = 0.f, s2 = 0.f;
            #pragma unroll
            for (int mt = 0; mt < 4; mt++) {
                int row = rowBase + warpM * 64 + mt * 16 + gID;
                #pragma unroll
                for (int hh = 0; hh < 2; hh++) {
                    float v = acc[mt][nt][p + 2 * hh] + bs;
                    s += v; s2 += v * v;
                    float o = v;
                    if (act == 1) o = fmaxf(o, 0.f);
                    else if (act == 2) o = gelu_tanh(o);
                    if (cv) C[(size_t)(row + 8 * hh) * N + col] = o;
                }
            }
            if (doStats && cv) {
                atomicAdd(&sstat[lc], s);
                atomicAdd(&sstat[128 + lc], s2);
            }
        }
    }
    if (doStats) {
        __syncthreads();
        if (tid < 128) {
            int col = colBase + tid;
            if (col < N) {
                atomicAdd(&stats[col], sstat[tid]);
                atomicAdd(&stats[N + col], sstat[128 + tid]);
            }
        }
    }
}

// ---------------- host orchestration ----------------
static inline int cdiv(long long a, long long b) { return (int)((a + b - 1) / b); }

static void launch_mma(int M, int N, int K, const float* A, const float* B,
                       const float* bias, float* C,
                       const float* aS, const float* aH, float* stats, int act) {
    dim3 grid(cdiv(N, 128), M / 128);
    k_mma<<<grid, 256>>>(M, N, K, A, B, bias, C, aS, aH, stats, act);
}

extern "C" void kernel_launch(void* const* d_in, const int* in_sizes, int n_in,
                              void* d_out, int out_size) {
    const int*   x_atom  = (const int*)  d_in[0];
    const int*   src     = (const int*)  d_in[1];
    const int*   dst     = (const int*)  d_in[2];
    const int*   eattr   = (const int*)  d_in[3];
    const int*   batch   = (const int*)  d_in[4];
    const float* fp      = (const float*)d_in[5];
    const float* atom_emb= (const float*)d_in[6];
    const float* edge_emb= (const float*)d_in[7];
    const float* eps     = (const float*)d_in[8];
    const float* W1  = (const float*)d_in[9];
    const float* b1  = (const float*)d_in[10];
    const float* g1  = (const float*)d_in[11];
    const float* be1 = (const float*)d_in[12];
    const float* W2  = (const float*)d_in[13];
    const float* b2  = (const float*)d_in[14];
    const float* bng = (const float*)d_in[15];
    const float* bnb = (const float*)d_in[16];
    const float* vW1 = (const float*)d_in[17];
    const float* vb1 = (const float*)d_in[18];
    const float* vg1 = (const float*)d_in[19];
    const float* vbe1= (const float*)d_in[20];
    const float* vW2 = (const float*)d_in[21];
    const float* vb2 = (const float*)d_in[22];
    const float* vg2 = (const float*)d_in[23];
    const float* vbe2= (const float*)d_in[24];
    const float* pW1 = (const float*)d_in[25];
    const float* pb1 = (const float*)d_in[26];
    const float* pW2 = (const float*)d_in[27];
    const float* pb2 = (const float*)d_in[28];
    float* out = (float*)d_out;

    float *p_h, *p_hl, *p_acc, *p_y1, *p_y2, *p_vn, *p_vt, *p_u1, *p_u2,
          *p_hg, *p_t1, *p_stats, *p_scale, *p_shift;
    cudaGetSymbolAddress((void**)&p_h,    g_h);
    cudaGetSymbolAddress((void**)&p_hl,   g_hl);
    cudaGetSymbolAddress((void**)&p_acc,  g_acc);
    cudaGetSymbolAddress((void**)&p_y1,   g_y1);
    cudaGetSymbolAddress((void**)&p_y2,   g_y2);
    cudaGetSymbolAddress((void**)&p_vn,   g_vn);
    cudaGetSymbolAddress((void**)&p_vt,   g_vt);
    cudaGetSymbolAddress((void**)&p_u1,   g_u1);
    cudaGetSymbolAddress((void**)&p_u2,   g_u2);
    cudaGetSymbolAddress((void**)&p_hg,   g_hg);
    cudaGetSymbolAddress((void**)&p_t1,   g_t1);
    cudaGetSymbolAddress((void**)&p_stats,g_stats);
    cudaGetSymbolAddress((void**)&p_scale,g_scale);
    cudaGetSymbolAddress((void**)&p_shift,g_shift);

    const size_t ND  = (size_t)NN * DD;
    const size_t GD  = (size_t)GG * DD;
    const size_t ND4 = ND / 4;

    k_zero<<<cdiv(GD, 256), 256>>>(p_vn, GD);
    k_embed<<<cdiv(ND4, 256), 256>>>(x_atom, atom_emb, p_h);

    for (int l = 0; l < LL; l++) {
        int doVt = (l < LL - 1);

        k_hl_acc<<<cdiv(ND4, 256), 256>>>(p_h, p_vn, batch, eps, l, p_hl, p_acc);

        k_edge<<<EE / 4, 300>>>(p_hl, edge_emb + (size_t)l * 5 * DD,
                                src, dst, eattr, p_acc);

        if (doVt)
            k_vt<<<GG, 128>>>(p_hl, batch, p_vn, p_vt);

        // GEMM1: acc[NN,300] @ W1[300,600] (+stats)
        k_zero<<<cdiv(2 * DD2, 256), 256>>>(p_stats, 2 * DD2);
        launch_mma(NN, DD2, DD, p_acc, W1 + (size_t)l * DD * DD2,
                   b1 + (size_t)l * DD2, p_y1, nullptr, nullptr, p_stats, 0);
        k_bnfinal<<<cdiv(DD2, 256), 256>>>(p_stats, g1 + (size_t)l * DD2,
                                           be1 + (size_t)l * DD2, NN, DD2,
                                           p_scale, p_shift);

        // GEMM2: relu(bn(y1))[NN,600] @ W2[600,300] (+stats); BN applied on A-load
        k_zero<<<cdiv(2 * DD, 256), 256>>>(p_stats, 2 * DD);
        launch_mma(NN, DD, DD2, p_y1, W2 + (size_t)l * DD2 * DD,
                   b2 + (size_t)l * DD, p_y2, p_scale, p_shift, p_stats, 0);
        k_bnfinal<<<cdiv(DD, 256), 256>>>(p_stats, bng + (size_t)l * DD,
                                          bnb + (size_t)l * DD, NN, DD,
                                          p_scale, p_shift);
        k_bnapply<<<cdiv(ND4, 256), 256>>>(p_y2, p_h, ND4, DD / 4,
                                           p_scale, p_shift, doVt ? 1 : 0);

        if (doVt) {
            k_zero<<<cdiv(2 * DD2, 256), 256>>>(p_stats, 2 * DD2);
            launch_mma(GG, DD2, DD, p_vt, vW1 + (size_t)l * DD * DD2,
                       vb1 + (size_t)l * DD2, p_u1, nullptr, nullptr, p_stats, 0);
            k_bnfinal<<<cdiv(DD2, 256), 256>>>(p_stats, vg1 + (size_t)l * DD2,
                                               vbe1 + (size_t)l * DD2, GG, DD2,
                                               p_scale, p_shift);

            k_zero<<<cdiv(2 * DD, 256), 256>>>(p_stats, 2 * DD);
            launch_mma(GG, DD, DD2, p_u1, vW2 + (size_t)l * DD2 * DD,
                       vb2 + (size_t)l * DD, p_u2, p_scale, p_shift, p_stats, 0);
            k_bnfinal<<<cdiv(DD, 256), 256>>>(p_stats, vg2 + (size_t)l * DD,
                                              vbe2 + (size_t)l * DD, GG, DD,
                                              p_scale, p_shift);
            k_bnapply<<<cdiv(GD / 4, 256), 256>>>(p_u2, p_vn, GD / 4, DD / 4,
                                                  p_scale, p_shift, 1);
        }
    }

    // head
    k_pool<<<GG, 256>>>(p_h, batch, fp, p_hg);
    launch_mma(GG, H1, HGC, p_hg, pW1, pb1, p_t1, nullptr, nullptr, nullptr, 2);
    launch_mma(GG, NT, H1, p_t1, pW2, pb2, out, nullptr, nullptr, nullptr, 0);
}